// round 11
// baseline (speedup 1.0000x reference)
#include <cuda_runtime.h>
#include <math.h>
#include <stdint.h>

// Problem constants
#define N_TOK   131072      // 32 * 4096 tokens
#define DIM     64
#define KCODES  1024
#define TT      128         // tokens per CTA
#define CK      64          // codes per chunk
#define NCHUNK  (KCODES / CK)   // 16
#define NB      (N_TOK / TT)    // 1024 CTAs
#define NTHREADS 256
#define WD_STR  66          // u64 stride per j row of duplicated W (even -> 16B lds ok)
#define WD_BUF  (64 * WD_STR)   // u64 per buffer = 4224

// smem float offsets
#define OFF_XS   0                          // xs[64][128]           : 8192
#define OFF_WD   8192                       // wdup[2][64][66] u64   : 16896
#define OFF_WSQ  25088                      // 1024
#define OFF_XSQ  26112                      // 128
#define SMEM_FLOATS 26240
#define SMEM_BYTES (SMEM_FLOATS * 4)        // 104960 B -> 2 CTAs fit in 227KB

// Scratch
__device__ float g_wsq[KCODES];
__device__ int   g_counts[KCODES];
__device__ float g_part[NB];

// ---- packed f32x2 helpers (baseline PTX; proven real HW in R10) ----
__device__ __forceinline__ void fma2(unsigned long long& acc,
                                     unsigned long long w2,
                                     unsigned long long x2) {
    asm("fma.rn.f32x2 %0, %1, %2, %0;" : "+l"(acc) : "l"(w2), "l"(x2));
}
__device__ __forceinline__ unsigned long long dup2(float v) {
    unsigned long long r;
    asm("mov.b64 %0, {%1, %1};" : "=l"(r) : "f"(v));
    return r;
}
__device__ __forceinline__ void unpack2(unsigned long long a, float& lo, float& hi) {
    asm("mov.b64 {%0, %1}, %2;" : "=f"(lo), "=f"(hi) : "l"(a));
}

// ---------------------------------------------------------------------------
// Kernel 0: wsq[k] = sum_j W[k][j]^2 (sequential), zero counts
// ---------------------------------------------------------------------------
__global__ void vq_prep(const float* __restrict__ W) {
    int k = blockIdx.x * blockDim.x + threadIdx.x;
    if (k < KCODES) {
        const float* row = W + (size_t)k * DIM;
        float s = 0.f;
        #pragma unroll
        for (int j = 0; j < DIM; ++j) s += row[j] * row[j];
        g_wsq[k]    = s;
        g_counts[k] = 0;
    }
}

// ---------------------------------------------------------------------------
// Kernel 1: packed-f32x2 GEMM, token-pair packing (zero per-j MOVs)
//   256 thr (8 warps). Tokens on lanes (4/thread = 2 packed pairs),
//   codes on warps (8/warp). W duplicated (w,w) in smem per chunk.
// ---------------------------------------------------------------------------
__global__ void __launch_bounds__(NTHREADS, 2)
vq_main(const float* __restrict__ x, const float* __restrict__ W,
        float* __restrict__ out)
{
    extern __shared__ float sf[];
    float* xs   = sf + OFF_XS;                       // [j][t]
    unsigned long long* wd = (unsigned long long*)(sf + OFF_WD);  // [2][j][66]
    float* wsq_s = sf + OFF_WSQ;
    float* xsq   = sf + OFF_XSQ;
    // union region inside wdup (valid after mainloop):
    float* bd   = sf + OFF_WD;                       // [8][128]
    int*   bi   = (int*)(sf + OFF_WD + 1024);        // [8][128]
    int*   fidx = (int*)(sf + OFF_WD + 2048);        // [128]
    float* red  = sf + OFF_WD;                       // loss reduce (after argmin)

    const int tid  = threadIdx.x;
    const int wid  = tid >> 5;
    const int lane = tid & 31;
    const int tbase = blockIdx.x * TT;
    const int t0 = lane * 4;                  // tokens t0..t0+3 (2 packed pairs)
    const int k0 = wid * 8;                   // this warp's 8 codes

    // ---- load x tile transposed ----
    for (int i = tid; i < TT * 16; i += NTHREADS) {
        int t  = i >> 4;
        int j4 = (i & 15) << 2;
        float4 v = *(const float4*)(x + (size_t)(tbase + t) * DIM + j4);
        xs[(j4 + 0) * TT + t] = v.x;
        xs[(j4 + 1) * TT + t] = v.y;
        xs[(j4 + 2) * TT + t] = v.z;
        xs[(j4 + 3) * TT + t] = v.w;
    }
    // wsq into smem
    for (int i = tid; i < KCODES; i += NTHREADS) wsq_s[i] = g_wsq[i];

    // ---- chunk 0: load W, store DUPLICATED (w,w) pairs transposed ----
    {
        #pragma unroll
        for (int q = 0; q < 4; ++q) {
            int i = tid + q * NTHREADS;
            int r = i >> 4, c4 = (i & 15) << 2;      // r = code, c4 = dim group
            float4 v = *(const float4*)(W + (size_t)r * DIM + c4);
            wd[(c4 + 0) * WD_STR + r] = dup2(v.x);
            wd[(c4 + 1) * WD_STR + r] = dup2(v.y);
            wd[(c4 + 2) * WD_STR + r] = dup2(v.z);
            wd[(c4 + 3) * WD_STR + r] = dup2(v.w);
        }
    }
    __syncthreads();

    // ---- xsq per token (sequential j, as reference/R1) ----
    if (tid < TT) {
        float s = 0.f;
        for (int j = 0; j < DIM; ++j) { float v = xs[j * TT + tid]; s += v * v; }
        xsq[tid] = s;
    }
    __syncthreads();
    float xsqr[4];
    #pragma unroll
    for (int c = 0; c < 4; ++c) xsqr[c] = xsq[t0 + c];

    float bestd[4]; int besti[4];
    #pragma unroll
    for (int c = 0; c < 4; ++c) { bestd[c] = 3.0e38f; besti[c] = 0; }

    for (int ch = 0; ch < NCHUNK; ++ch) {
        const int b = ch & 1;

        // register-prefetch next chunk
        float4 pf[4];
        if (ch + 1 < NCHUNK) {
            const float* src = W + (size_t)(ch + 1) * CK * DIM;
            #pragma unroll
            for (int q = 0; q < 4; ++q) {
                int i = tid + q * NTHREADS;
                int r = i >> 4, c4 = (i & 15) << 2;
                pf[q] = *(const float4*)(src + (size_t)r * DIM + c4);
            }
        }

        const unsigned long long* wb = wd + b * WD_BUF + k0;

        unsigned long long acc[2][8];     // [token-pair][code]
        #pragma unroll
        for (int p = 0; p < 2; ++p)
            #pragma unroll
            for (int k = 0; k < 8; ++k) acc[p][k] = 0ull;

        #pragma unroll 8
        for (int j = 0; j < DIM; ++j) {
            // x: tokens t0..t0+3 = two ready-made f32x2 pairs, one LDS.128
            ulonglong2 xp = *(const ulonglong2*)(xs + j * TT + t0);
            // w: 8 duplicated codes, warp-broadcast, 4x LDS.128
            const ulonglong2* wp = (const ulonglong2*)(wb + (size_t)j * WD_STR);
            ulonglong2 w01 = wp[0], w23 = wp[1], w45 = wp[2], w67 = wp[3];
            fma2(acc[0][0], w01.x, xp.x); fma2(acc[1][0], w01.x, xp.y);
            fma2(acc[0][1], w01.y, xp.x); fma2(acc[1][1], w01.y, xp.y);
            fma2(acc[0][2], w23.x, xp.x); fma2(acc[1][2], w23.x, xp.y);
            fma2(acc[0][3], w23.y, xp.x); fma2(acc[1][3], w23.y, xp.y);
            fma2(acc[0][4], w45.x, xp.x); fma2(acc[1][4], w45.x, xp.y);
            fma2(acc[0][5], w45.y, xp.x); fma2(acc[1][5], w45.y, xp.y);
            fma2(acc[0][6], w67.x, xp.x); fma2(acc[1][6], w67.x, xp.y);
            fma2(acc[0][7], w67.y, xp.x); fma2(acc[1][7], w67.y, xp.y);
        }

        // distances + running argmin (codes ascending -> lowest-index ties)
        const int kg0 = ch * CK + k0;
        #pragma unroll
        for (int k = 0; k < 8; ++k) {
            float wsqk = wsq_s[kg0 + k];
            float d0, d1, d2, d3;
            unpack2(acc[0][k], d0, d1);       // dots: tokens t0, t0+1
            unpack2(acc[1][k], d2, d3);       // dots: tokens t0+2, t0+3
            float d;
            d = fmaf(-2.f, d0, wsqk + xsqr[0]);
            if (d < bestd[0]) { bestd[0] = d; besti[0] = kg0 + k; }
            d = fmaf(-2.f, d1, wsqk + xsqr[1]);
            if (d < bestd[1]) { bestd[1] = d; besti[1] = kg0 + k; }
            d = fmaf(-2.f, d2, wsqk + xsqr[2]);
            if (d < bestd[2]) { bestd[2] = d; besti[2] = kg0 + k; }
            d = fmaf(-2.f, d3, wsqk + xsqr[3]);
            if (d < bestd[3]) { bestd[3] = d; besti[3] = kg0 + k; }
        }

        // store prefetched chunk DUPLICATED into other buffer
        if (ch + 1 < NCHUNK) {
            unsigned long long* dst = wd + (b ^ 1) * WD_BUF;
            #pragma unroll
            for (int q = 0; q < 4; ++q) {
                int i = tid + q * NTHREADS;
                int r = i >> 4, c4 = (i & 15) << 2;
                dst[(c4 + 0) * WD_STR + r] = dup2(pf[q].x);
                dst[(c4 + 1) * WD_STR + r] = dup2(pf[q].y);
                dst[(c4 + 2) * WD_STR + r] = dup2(pf[q].z);
                dst[(c4 + 3) * WD_STR + r] = dup2(pf[q].w);
            }
        }
        __syncthreads();
    }

    // ---- cross-warp argmin reduction (wdup region now reusable) ----
    #pragma unroll
    for (int c = 0; c < 4; ++c) {
        bd[wid * TT + t0 + c] = bestd[c];
        bi[wid * TT + t0 + c] = besti[c];
    }
    __syncthreads();
    if (tid < TT) {
        float bdv = bd[tid]; int biv = bi[tid];
        #pragma unroll
        for (int w = 1; w < 8; ++w) {
            float d2 = bd[w * TT + tid]; int i2 = bi[w * TT + tid];
            if (d2 < bdv || (d2 == bdv && i2 < biv)) { bdv = d2; biv = i2; }
        }
        fidx[tid] = biv;
        atomicAdd(&g_counts[biv], 1);
    }
    __syncthreads();

    // ---- epilogue: quantized_st + loss partial (as R1) ----
    float ls = 0.f;
    for (int s = tid; s < TT * 2; s += NTHREADS) {
        int t  = s >> 1;
        int j0 = (s & 1) * 32;
        int kb = fidx[t];
        const float* wrow = W + (size_t)kb * DIM + j0;
        float* orow = out + (size_t)(tbase + t) * DIM + j0;
        #pragma unroll
        for (int jj = 0; jj < 32; jj += 4) {
            float4 w4 = *(const float4*)(wrow + jj);
            float4 o;
            float xv, dq;
            xv = xs[(j0 + jj + 0) * TT + t]; dq = w4.x - xv; o.x = xv + dq; ls = fmaf(dq, dq, ls);
            xv = xs[(j0 + jj + 1) * TT + t]; dq = w4.y - xv; o.y = xv + dq; ls = fmaf(dq, dq, ls);
            xv = xs[(j0 + jj + 2) * TT + t]; dq = w4.z - xv; o.z = xv + dq; ls = fmaf(dq, dq, ls);
            xv = xs[(j0 + jj + 3) * TT + t]; dq = w4.w - xv; o.w = xv + dq; ls = fmaf(dq, dq, ls);
            *(float4*)(orow + jj) = o;
        }
    }

    __syncthreads();
    red[tid] = ls;
    __syncthreads();
    for (int off = NTHREADS / 2; off > 0; off >>= 1) {
        if (tid < off) red[tid] += red[tid + off];
        __syncthreads();
    }
    if (tid == 0) g_part[blockIdx.x] = red[0];
}

// ---------------------------------------------------------------------------
// Kernel 2: final scalars (loss, perplexity, usage)
// ---------------------------------------------------------------------------
__global__ void vq_final(float* __restrict__ out, int out_size) {
    __shared__ float red[1024];
    __shared__ float red2[1024];
    int tid = threadIdx.x;

    red[tid] = g_part[tid];
    __syncthreads();
    for (int off = 512; off > 0; off >>= 1) {
        if (tid < off) red[tid] += red[tid + off];
        __syncthreads();
    }
    float sse = red[0];
    __syncthreads();

    int c  = g_counts[tid];
    float p = (float)c / (float)N_TOK;
    red[tid]  = p * logf(p + 1e-10f);
    red2[tid] = (c >= 1) ? 1.f : 0.f;
    __syncthreads();
    for (int off = 512; off > 0; off >>= 1) {
        if (tid < off) { red[tid] += red[tid + off]; red2[tid] += red2[tid + off]; }
        __syncthreads();
    }
    if (tid == 0 && out_size >= N_TOK * DIM + 3) {
        float mse = sse / (float)(N_TOK * DIM);
        out[N_TOK * DIM + 0] = mse + 2.0f * mse;   // q_latent + COMMITMENT_COST*e_latent
        out[N_TOK * DIM + 1] = expf(-red[0]);
        out[N_TOK * DIM + 2] = red2[0];
    }
}

// ---------------------------------------------------------------------------
extern "C" void kernel_launch(void* const* d_in, const int* in_sizes, int n_in,
                              void* d_out, int out_size) {
    const float* x = (const float*)d_in[0];   // [32,4096,64] f32
    const float* W = (const float*)d_in[1];   // [1024,64] f32
    float* out = (float*)d_out;

    cudaFuncSetAttribute(vq_main, cudaFuncAttributeMaxDynamicSharedMemorySize,
                         SMEM_BYTES);

    vq_prep<<<8, 128>>>(W);
    vq_main<<<NB, NTHREADS, SMEM_BYTES>>>(x, W, out);
    vq_final<<<1, 1024>>>(out, out_size);
}